// round 4
// baseline (speedup 1.0000x reference)
#include <cuda_runtime.h>
#include <cstdint>
#include <cstring>

#define HH 8
#define DD 1024
#define SS 1024
#define MIDD 2048
#define SOUT 512

typedef long long ll;
typedef unsigned long long u64;

// ---------------- scratch (device globals; no allocation allowed) ----------
__device__ float g_qkv[3ll * DD * SS];          // 12 MB (block1 qkv; slot0 reused for q2)
__device__ float g_z[(ll)HH * DD * MIDD];       // 64 MB
__device__ float g_s[(ll)HH * 3 * DD * SS];     // 96 MB
__device__ float g_bm[(ll)HH * SS * SS];        // 32 MB
__device__ float g_att[(ll)HH * DD * SS];       // 32 MB
__device__ float g_y[(ll)SS * MIDD];            // 8 MB
__device__ float g_m[(ll)DD * SS];              // 4 MB
__device__ float g_h[(ll)DD * SS];              // 4 MB
__device__ float g_x1[(ll)DD * MIDD];           // 8 MB
__device__ float g_x2[(ll)DD * SOUT];           // 2 MB

// ---------------- packed f32x2 helpers (sm_103a FFMA2) ----------------------
__device__ __forceinline__ void ffma2(u64& d, u64 a, u64 b) {
    asm("fma.rn.f32x2 %0, %1, %2, %0;" : "+l"(d) : "l"(a), "l"(b));
}
__device__ __forceinline__ u64 bcast2(float x) {
    u64 r;
    asm("mov.b64 %0, {%1, %1};" : "=l"(r) : "f"(x));
    return r;
}

// ---------------- generic batched SGEMM ------------------------------------
// C[M,N] = act(op(A)) @ act(op(B)), row-major.
//   TA: A stored as (K,M). TB: B stored as (N,K). RA/RB: ReLU on operand load.
//   TH: tanh epilogue. M,N multiples of 128; K multiples of 8.

#define BM 128
#define BN 128
#define BK 8

__device__ __forceinline__ float4 relu4(float4 v) {
    v.x = fmaxf(v.x, 0.f); v.y = fmaxf(v.y, 0.f);
    v.z = fmaxf(v.z, 0.f); v.w = fmaxf(v.w, 0.f);
    return v;
}

template<bool TA, bool TB, bool RA, bool RB, bool TH>
__global__ __launch_bounds__(256) void gemm_k(
    const float* __restrict__ Ag, const float* __restrict__ Bg, float* __restrict__ Cg,
    int M, int N, int K, ll sA, ll sB, ll sC)
{
    const float* A = Ag + (ll)blockIdx.z * sA;
    const float* B = Bg + (ll)blockIdx.z * sB;
    float*       C = Cg + (ll)blockIdx.z * sC;
    const int m0 = blockIdx.y * BM;
    const int n0 = blockIdx.x * BN;

    __shared__ __align__(16) float As[BK][BM];
    __shared__ __align__(16) float Bs[BK][BN];

    const int tid = threadIdx.x;        // 0..255
    const int tx  = tid & 15;
    const int ty  = tid >> 4;

    // 8x8 micro-tile held as 8x4 packed f32x2 pairs along j
    u64 acc[8][4];
    #pragma unroll
    for (int i = 0; i < 8; i++)
        #pragma unroll
        for (int jp = 0; jp < 4; jp++)
            acc[i][jp] = 0ull;

    for (int k0 = 0; k0 < K; k0 += BK) {
        float4 av, bv;
        int am, ak, bn, bk;
        if (!TA) {                       // A (M,K): float4 along K
            am = tid >> 1; ak = (tid & 1) * 4;
            av = *(const float4*)(A + (ll)(m0 + am) * K + k0 + ak);
        } else {                         // A (K,M): float4 along M
            ak = tid >> 5; am = (tid & 31) * 4;
            av = *(const float4*)(A + (ll)(k0 + ak) * M + m0 + am);
        }
        if (RA) av = relu4(av);
        if (!TB) {                       // B (K,N): float4 along N
            bk = tid >> 5; bn = (tid & 31) * 4;
            bv = *(const float4*)(B + (ll)(k0 + bk) * N + n0 + bn);
        } else {                         // B (N,K): float4 along K
            bn = tid >> 1; bk = (tid & 1) * 4;
            bv = *(const float4*)(B + (ll)(n0 + bn) * K + k0 + bk);
        }
        if (RB) bv = relu4(bv);

        if (!TA) {
            As[ak + 0][am] = av.x; As[ak + 1][am] = av.y;
            As[ak + 2][am] = av.z; As[ak + 3][am] = av.w;
        } else {
            *(float4*)&As[ak][am] = av;
        }
        if (!TB) {
            *(float4*)&Bs[bk][bn] = bv;
        } else {
            Bs[bk + 0][bn] = bv.x; Bs[bk + 1][bn] = bv.y;
            Bs[bk + 2][bn] = bv.z; Bs[bk + 3][bn] = bv.w;
        }
        __syncthreads();

        #pragma unroll
        for (int k = 0; k < BK; k++) {
            float a[8];
            *(float4*)&a[0] = *(const float4*)&As[k][ty * 8];
            *(float4*)&a[4] = *(const float4*)&As[k][ty * 8 + 4];
            // B fragment read directly as packed f32x2 pairs (no pack cost)
            u64 bp[4];
            *(ulonglong2*)&bp[0] = *(const ulonglong2*)&Bs[k][tx * 8];
            *(ulonglong2*)&bp[2] = *(const ulonglong2*)&Bs[k][tx * 8 + 4];
            #pragma unroll
            for (int i = 0; i < 8; i++) {
                const u64 ap = bcast2(a[i]);
                #pragma unroll
                for (int jp = 0; jp < 4; jp++)
                    ffma2(acc[i][jp], ap, bp[jp]);
            }
        }
        __syncthreads();
    }

    #pragma unroll
    for (int i = 0; i < 8; i++) {
        float* crow = C + (ll)(m0 + ty * 8 + i) * N + n0 + tx * 8;
        float o[8];
        #pragma unroll
        for (int jp = 0; jp < 4; jp++) {
            float2 v;
            memcpy(&v, &acc[i][jp], 8);
            o[2 * jp]     = v.x;
            o[2 * jp + 1] = v.y;
        }
        #pragma unroll
        for (int j = 0; j < 8; j += 4) {
            float4 v = make_float4(o[j], o[j+1], o[j+2], o[j+3]);
            if (TH) { v.x = tanhf(v.x); v.y = tanhf(v.y); v.z = tanhf(v.z); v.w = tanhf(v.w); }
            *(float4*)(crow + j) = v;
        }
    }
}

// ---------------- fused residual-add + LayerNorm (rows of length S=1024) ----
__global__ __launch_bounds__(256) void add_ln_k(
    const float* __restrict__ x, const float* __restrict__ m,
    const float* __restrict__ g, const float* __restrict__ b,
    float* __restrict__ o)
{
    const int row = blockIdx.x;
    const ll off = (ll)row * SS;
    float v[4];
    float sum = 0.f, sq = 0.f;
    #pragma unroll
    for (int j = 0; j < 4; j++) {
        int i = threadIdx.x + j * 256;
        v[j] = x[off + i] + m[off + i];
        sum += v[j];
        sq  += v[j] * v[j];
    }
    #pragma unroll
    for (int o2 = 16; o2; o2 >>= 1) {
        sum += __shfl_xor_sync(0xffffffffu, sum, o2);
        sq  += __shfl_xor_sync(0xffffffffu, sq,  o2);
    }
    __shared__ float rs[8], rq[8];
    const int w = threadIdx.x >> 5, l = threadIdx.x & 31;
    if (l == 0) { rs[w] = sum; rq[w] = sq; }
    __syncthreads();
    if (w == 0) {
        float s2 = (l < 8) ? rs[l] : 0.f;
        float q2 = (l < 8) ? rq[l] : 0.f;
        #pragma unroll
        for (int o2 = 4; o2; o2 >>= 1) {
            s2 += __shfl_xor_sync(0xffffffffu, s2, o2);
            q2 += __shfl_xor_sync(0xffffffffu, q2, o2);
        }
        if (l == 0) { rs[0] = s2; rq[0] = q2; }
    }
    __syncthreads();
    const float mu  = rs[0] * (1.f / SS);
    const float var = rq[0] * (1.f / SS) - mu * mu;
    const float inv = rsqrtf(var + 1e-6f);
    #pragma unroll
    for (int j = 0; j < 4; j++) {
        int i = threadIdx.x + j * 256;
        o[off + i] = (v[j] - mu) * inv * g[i] + b[i];
    }
}

// ---------------- host orchestration ----------------------------------------
extern "C" void kernel_launch(void* const* d_in, const int* in_sizes, int n_in,
                              void* d_out, int out_size)
{
    const float* inp    = (const float*)d_in[0];
    const float* enc_k  = (const float*)d_in[1];
    const float* enc_v  = (const float*)d_in[2];
    const float* w_qkv1 = (const float*)d_in[3];
    const float* w_qkv2 = (const float*)d_in[4];
    const float* mh1_W1 = (const float*)d_in[5];
    const float* mh1_W2 = (const float*)d_in[6];
    const float* mh2_W1 = (const float*)d_in[7];
    const float* mh2_W2 = (const float*)d_in[8];
    const float* c1_w1  = (const float*)d_in[9];
    const float* c1_w2  = (const float*)d_in[10];
    const float* c2_w1  = (const float*)d_in[11];
    const float* c2_w2  = (const float*)d_in[12];
    const float* l1_w1  = (const float*)d_in[13];
    const float* l1_w2  = (const float*)d_in[14];
    const float* l2_w1  = (const float*)d_in[15];
    const float* l2_w2  = (const float*)d_in[16];
    const float* gamma  = (const float*)d_in[17];
    const float* beta   = (const float*)d_in[18];
    float* out = (float*)d_out;

    float *qkv, *z, *s, *bm, *att, *y, *mb, *hb, *x1, *x2;
    cudaGetSymbolAddress((void**)&qkv, g_qkv);
    cudaGetSymbolAddress((void**)&z,   g_z);
    cudaGetSymbolAddress((void**)&s,   g_s);
    cudaGetSymbolAddress((void**)&bm,  g_bm);
    cudaGetSymbolAddress((void**)&att, g_att);
    cudaGetSymbolAddress((void**)&y,   g_y);
    cudaGetSymbolAddress((void**)&mb,  g_m);
    cudaGetSymbolAddress((void**)&hb,  g_h);
    cudaGetSymbolAddress((void**)&x1,  g_x1);
    cudaGetSymbolAddress((void**)&x2,  g_x2);

    const ll DS = (ll)DD * SS;

    auto run_block = [&](const float* qp0, const float* qp1, const float* qp2,
                         const float* W1, const float* W2,
                         const float* cw1, const float* cw2) {
        const float* qp[3] = {qp0, qp1, qp2};
        for (int q = 0; q < 3; q++) {
            // z[h] = relu(qkv[q]) @ W1[h,q]^T      (D x MID, K=S), batch h
            gemm_k<false, true, true, false, false>
                <<<dim3(MIDD / BN, DD / BM, HH), 256>>>(
                    qp[q], W1 + (ll)q * MIDD * SS, z,
                    DD, MIDD, SS, 0, 3ll * MIDD * SS, (ll)DD * MIDD);
            // s[h,q] = relu(z[h]) @ W2[h,q]^T      (D x S, K=MID), batch h
            gemm_k<false, true, true, false, false>
                <<<dim3(SS / BN, DD / BM, HH), 256>>>(
                    z, W2 + (ll)q * SS * MIDD, s + (ll)q * DS,
                    DD, SS, MIDD, (ll)DD * MIDD, 3ll * SS * MIDD, 3ll * DS);
        }
        // b[h] = k[h]^T @ q[h]                      (S x S, K=D), batch h
        gemm_k<true, false, false, false, false>
            <<<dim3(SS / BN, SS / BM, HH), 256>>>(
                s + DS, s, bm, SS, SS, DD, 3ll * DS, 3ll * DS, (ll)SS * SS);
        // att[h] = v[h] @ b[h]                      (D x S, K=S), batch h
        gemm_k<false, false, false, false, false>
            <<<dim3(SS / BN, DD / BM, HH), 256>>>(
                s + 2ll * DS, bm, att, DD, SS, SS, 3ll * DS, (ll)SS * SS, DS);
        // y[s,m] = sum_c relu(cat[c,s]) * cw1[m,c]  (S x MID, K=H*D)
        gemm_k<true, true, true, false, false>
            <<<dim3(MIDD / BN, SS / BM, 1), 256>>>(
                att, cw1, y, SS, MIDD, HH * DD, 0, 0, 0);
        // m[d,s] = sum_m cw2[d,m] * relu(y[s,m])    (D x S, K=MID)
        gemm_k<false, true, false, true, false>
            <<<dim3(SS / BN, DD / BM, 1), 256>>>(
                cw2, y, mb, DD, SS, MIDD, 0, 0, 0);
    };

    // qkv1[q] = w_qkv1[q] @ inp                     (D x S, K=D), batch 3
    gemm_k<false, false, false, false, false>
        <<<dim3(SS / BN, DD / BM, 3), 256>>>(
            w_qkv1, inp, qkv, DD, SS, DD, (ll)DD * DD, 0, DS);

    run_block(qkv, qkv + DS, qkv + 2ll * DS, mh1_W1, mh1_W2, c1_w1, c1_w2);
    add_ln_k<<<DD, 256>>>(inp, mb, gamma, beta, hb);

    // q2 = w_qkv2[0] @ h1  -> reuse qkv slot 0
    gemm_k<false, false, false, false, false>
        <<<dim3(SS / BN, DD / BM, 1), 256>>>(
            w_qkv2, hb, qkv, DD, SS, DD, 0, 0, 0);

    run_block(qkv, enc_k, enc_v, mh2_W1, mh2_W2, c2_w1, c2_w2);
    add_ln_k<<<DD, 256>>>(inp, mb, gamma, beta, hb);

    // x1 = relu(h2) @ l1_w1^T                       (D x MID, K=S)
    gemm_k<false, true, true, false, false>
        <<<dim3(MIDD / BN, DD / BM, 1), 256>>>(hb, l1_w1, x1, DD, MIDD, SS, 0, 0, 0);
    // x2 = relu(x1) @ l1_w2^T                       (D x SOUT, K=MID)
    gemm_k<false, true, true, false, false>
        <<<dim3(SOUT / BN, DD / BM, 1), 256>>>(x1, l1_w2, x2, DD, SOUT, MIDD, 0, 0, 0);
    // y1 = relu(x2) @ l2_w1^T                       (D x MID, K=SOUT)
    gemm_k<false, true, true, false, false>
        <<<dim3(MIDD / BN, DD / BM, 1), 256>>>(x2, l2_w1, x1, DD, MIDD, SOUT, 0, 0, 0);
    // out = tanh(relu(y1) @ l2_w2^T)                (D x SOUT, K=MID)
    gemm_k<false, true, true, false, true>
        <<<dim3(SOUT / BN, DD / BM, 1), 256>>>(x1, l2_w2, out, DD, SOUT, MIDD, 0, 0, 0);
}

// round 10
// speedup vs baseline: 2.5415x; 2.5415x over previous
#include <cuda_runtime.h>
#include <cstdint>

#define HH 8
#define DD 1024
#define SS 1024
#define MIDD 2048
#define SOUT 512

typedef long long ll;

// ---------------- scratch (device globals; no allocation allowed) ----------
__device__ float g_qkv[3ll * DD * SS];
__device__ float g_z[(ll)HH * DD * MIDD];
__device__ float g_s[(ll)HH * 3 * DD * SS];
__device__ float g_bm[(ll)HH * SS * SS];
__device__ float g_att[(ll)HH * DD * SS];
__device__ float g_y[(ll)SS * MIDD];
__device__ float g_m[(ll)DD * SS];
__device__ float g_h[(ll)DD * SS];
__device__ float g_x1[(ll)DD * MIDD];
__device__ float g_x2[(ll)DD * SOUT];

// ---------------- PTX helpers (all base sm_103 features) --------------------
__device__ __forceinline__ uint32_t smem_u32(const void* p) {
    uint32_t a;
    asm("{ .reg .u64 t; cvta.to.shared.u64 t, %1; cvt.u32.u64 %0, t; }"
        : "=r"(a) : "l"(p));
    return a;
}
__device__ __forceinline__ void cpa16(uint32_t dst, const float* src) {
    asm volatile("cp.async.cg.shared.global [%0], [%1], 16;"
                 :: "r"(dst), "l"(src) : "memory");
}
__device__ __forceinline__ void cpa4(uint32_t dst, const float* src) {
    asm volatile("cp.async.ca.shared.global [%0], [%1], 4;"
                 :: "r"(dst), "l"(src) : "memory");
}
__device__ __forceinline__ void cp_commit() {
    asm volatile("cp.async.commit_group;" ::: "memory");
}
template<int NG>
__device__ __forceinline__ void cp_wait() {
    asm volatile("cp.async.wait_group %0;" :: "n"(NG) : "memory");
}

// two-term bf16 split of a float2 (consecutive-k pair):
//   hi = packed bf16x2 of (x, y); lo = packed bf16x2 of residuals
template<bool R>
__device__ __forceinline__ void frag2(float2 v, uint32_t& hi, uint32_t& lo) {
    if (R) { v.x = fmaxf(v.x, 0.f); v.y = fmaxf(v.y, 0.f); }
    asm("cvt.rn.bf16x2.f32 %0, %1, %2;" : "=r"(hi) : "f"(v.y), "f"(v.x));
    const float hx = __uint_as_float(hi << 16);
    const float hy = __uint_as_float(hi & 0xffff0000u);
    const float lx = v.x - hx;
    const float ly = v.y - hy;
    asm("cvt.rn.bf16x2.f32 %0, %1, %2;" : "=r"(lo) : "f"(ly), "f"(lx));
}

__device__ __forceinline__ void mma16(float* d, const uint32_t* a, const uint32_t* b) {
    asm volatile(
        "mma.sync.aligned.m16n8k16.row.col.f32.bf16.bf16.f32 "
        "{%0,%1,%2,%3}, {%4,%5,%6,%7}, {%8,%9}, {%0,%1,%2,%3};"
        : "+f"(d[0]), "+f"(d[1]), "+f"(d[2]), "+f"(d[3])
        : "r"(a[0]), "r"(a[1]), "r"(a[2]), "r"(a[3]), "r"(b[0]), "r"(b[1]));
}

// ---------------- bf16x3 mma.sync GEMM --------------------------------------
// D[m][n] = sum_k act(a[m][k]) * act(b[n][k])      (fp32 accumulate)
//   LA=0: A stored (M,K) row-major.  LA=1: A stored (K,M).
//   LB=0: B stored (N,K) row-major.  LB=1: B stored (K,N).
//   RA/RB: ReLU on operand elements.  TH: tanh epilogue.
// M,N multiples of 128; K multiple of 32. 256 threads (8 warps, 2x4 warp grid).

#define STR     40                 // padded SMEM row stride in floats (LDS.64 conflict-free)
#define TILE_F  (128 * STR)        // floats per operand stage (5120)
#define STAGE_B (TILE_F * 4)       // 20480 bytes
#define SMEM_DYN (4 * STAGE_B)     // A0,B0,A1,B1 = 81920 bytes

template<int LA, int LB, bool RA, bool RB, bool TH>
__global__ __launch_bounds__(256, 2) void gemm_tc(
    const float* __restrict__ Ag, const float* __restrict__ Bg, float* __restrict__ Cg,
    int M, int N, int K, ll sA, ll sB, ll sC)
{
    extern __shared__ __align__(16) float smem[];
    const uint32_t sb = smem_u32(smem);

    const float* A = Ag + (ll)blockIdx.z * sA;
    const float* B = Bg + (ll)blockIdx.z * sB;
    float*       C = Cg + (ll)blockIdx.z * sC;
    const int m0 = blockIdx.y * 128;
    const int n0 = blockIdx.x * 128;

    const int tid = threadIdx.x;
    const int wid = tid >> 5, lid = tid & 31;
    const int wm = wid >> 2, wn = wid & 3;        // 2 x 4 warp grid
    const int g = lid >> 2, tg = lid & 3;

    float acc[4][4][4];
    #pragma unroll
    for (int mi = 0; mi < 4; mi++)
        #pragma unroll
        for (int ni = 0; ni < 4; ni++)
            #pragma unroll
            for (int r = 0; r < 4; r++) acc[mi][ni][r] = 0.f;

    auto issue = [&](int t) {
        const int st = t & 1;
        const uint32_t abase = sb + (uint32_t)(st * 2) * STAGE_B;
        const uint32_t bbase = abase + STAGE_B;
        const int k0 = t << 5;
        if (LA == 0) {
            #pragma unroll
            for (int i = 0; i < 4; i++) {
                int idx = tid + i * 256;
                int r = idx >> 3, kq = (idx & 7) << 2;
                cpa16(abase + (uint32_t)(r * STR + kq) * 4,
                      A + (ll)(m0 + r) * K + k0 + kq);
            }
        } else {
            #pragma unroll
            for (int i = 0; i < 16; i++) {
                int idx = tid + i * 256;
                int m = idx & 127, k = idx >> 7;
                cpa4(abase + (uint32_t)(m * STR + k) * 4,
                     A + (ll)(k0 + k) * M + m0 + m);
            }
        }
        if (LB == 0) {
            #pragma unroll
            for (int i = 0; i < 4; i++) {
                int idx = tid + i * 256;
                int r = idx >> 3, kq = (idx & 7) << 2;
                cpa16(bbase + (uint32_t)(r * STR + kq) * 4,
                      B + (ll)(n0 + r) * K + k0 + kq);
            }
        } else {
            #pragma unroll
            for (int i = 0; i < 16; i++) {
                int idx = tid + i * 256;
                int n = idx & 127, k = idx >> 7;
                cpa4(bbase + (uint32_t)(n * STR + k) * 4,
                     B + (ll)(k0 + k) * N + n0 + n);
            }
        }
    };

    const int T = K >> 5;
    issue(0);
    cp_commit();

    for (int t = 0; t < T; t++) {
        if (t + 1 < T) { issue(t + 1); cp_commit(); cp_wait<1>(); }
        else           { cp_wait<0>(); }
        __syncthreads();

        const float* As = smem + (t & 1) * 2 * TILE_F;
        const float* Bs = As + TILE_F;

        #pragma unroll
        for (int ks = 0; ks < 2; ks++) {            // two k16 steps per BK=32
            const int kb = ks * 16;
            // B fragments for all 4 ni (hi/lo)
            uint32_t bh[4][2], bl[4][2];
            #pragma unroll
            for (int ni = 0; ni < 4; ni++) {
                const float* p = Bs + (wn * 32 + ni * 8 + g) * STR + kb + 2 * tg;
                frag2<RB>(*(const float2*)(p),     bh[ni][0], bl[ni][0]);
                frag2<RB>(*(const float2*)(p + 8), bh[ni][1], bl[ni][1]);
            }
            #pragma unroll
            for (int mi = 0; mi < 4; mi++) {
                uint32_t ah[4], al[4];
                const float* p = As + (wm * 64 + mi * 16 + g) * STR + kb + 2 * tg;
                frag2<RA>(*(const float2*)(p),                ah[0], al[0]);
                frag2<RA>(*(const float2*)(p + 8 * STR),      ah[1], al[1]);
                frag2<RA>(*(const float2*)(p + 8),            ah[2], al[2]);
                frag2<RA>(*(const float2*)(p + 8 * STR + 8),  ah[3], al[3]);
                #pragma unroll
                for (int ni = 0; ni < 4; ni++) {
                    mma16(acc[mi][ni], ah, bh[ni]);
                    mma16(acc[mi][ni], ah, bl[ni]);
                    mma16(acc[mi][ni], al, bh[ni]);
                }
            }
        }
        __syncthreads();
    }

    // ---- epilogue: fragment layout -> global ----
    #pragma unroll
    for (int mi = 0; mi < 4; mi++) {
        #pragma unroll
        for (int ni = 0; ni < 4; ni++) {
            const int r0 = m0 + wm * 64 + mi * 16 + g;
            const int c  = n0 + wn * 32 + ni * 8 + 2 * tg;
            float2 v0 = make_float2(acc[mi][ni][0], acc[mi][ni][1]);
            float2 v1 = make_float2(acc[mi][ni][2], acc[mi][ni][3]);
            if (TH) {
                v0.x = tanhf(v0.x); v0.y = tanhf(v0.y);
                v1.x = tanhf(v1.x); v1.y = tanhf(v1.y);
            }
            *(float2*)(C + (ll)r0 * N + c)       = v0;
            *(float2*)(C + (ll)(r0 + 8) * N + c) = v1;
        }
    }
}

// ---------------- fused residual-add + LayerNorm -----------------------------
__global__ __launch_bounds__(256) void add_ln_k(
    const float* __restrict__ x, const float* __restrict__ m,
    const float* __restrict__ g, const float* __restrict__ b,
    float* __restrict__ o)
{
    const int row = blockIdx.x;
    const ll off = (ll)row * SS;
    float v[4];
    float sum = 0.f, sq = 0.f;
    #pragma unroll
    for (int j = 0; j < 4; j++) {
        int i = threadIdx.x + j * 256;
        v[j] = x[off + i] + m[off + i];
        sum += v[j];
        sq  += v[j] * v[j];
    }
    #pragma unroll
    for (int o2 = 16; o2; o2 >>= 1) {
        sum += __shfl_xor_sync(0xffffffffu, sum, o2);
        sq  += __shfl_xor_sync(0xffffffffu, sq,  o2);
    }
    __shared__ float rs[8], rq[8];
    const int w = threadIdx.x >> 5, l = threadIdx.x & 31;
    if (l == 0) { rs[w] = sum; rq[w] = sq; }
    __syncthreads();
    if (w == 0) {
        float s2 = (l < 8) ? rs[l] : 0.f;
        float q2 = (l < 8) ? rq[l] : 0.f;
        #pragma unroll
        for (int o2 = 4; o2; o2 >>= 1) {
            s2 += __shfl_xor_sync(0xffffffffu, s2, o2);
            q2 += __shfl_xor_sync(0xffffffffu, q2, o2);
        }
        if (l == 0) { rs[0] = s2; rq[0] = q2; }
    }
    __syncthreads();
    const float mu  = rs[0] * (1.f / SS);
    const float var = rq[0] * (1.f / SS) - mu * mu;
    const float inv = rsqrtf(var + 1e-6f);
    #pragma unroll
    for (int j = 0; j < 4; j++) {
        int i = threadIdx.x + j * 256;
        o[off + i] = (v[j] - mu) * inv * g[i] + b[i];
    }
}

// ---------------- host orchestration ----------------------------------------
extern "C" void kernel_launch(void* const* d_in, const int* in_sizes, int n_in,
                              void* d_out, int out_size)
{
    const float* inp    = (const float*)d_in[0];
    const float* enc_k  = (const float*)d_in[1];
    const float* enc_v  = (const float*)d_in[2];
    const float* w_qkv1 = (const float*)d_in[3];
    const float* w_qkv2 = (const float*)d_in[4];
    const float* mh1_W1 = (const float*)d_in[5];
    const float* mh1_W2 = (const float*)d_in[6];
    const float* mh2_W1 = (const float*)d_in[7];
    const float* mh2_W2 = (const float*)d_in[8];
    const float* c1_w1  = (const float*)d_in[9];
    const float* c1_w2  = (const float*)d_in[10];
    const float* c2_w1  = (const float*)d_in[11];
    const float* c2_w2  = (const float*)d_in[12];
    const float* l1_w1  = (const float*)d_in[13];
    const float* l1_w2  = (const float*)d_in[14];
    const float* l2_w1  = (const float*)d_in[15];
    const float* l2_w2  = (const float*)d_in[16];
    const float* gamma  = (const float*)d_in[17];
    const float* beta   = (const float*)d_in[18];
    float* out = (float*)d_out;

    float *qkv, *z, *s, *bm, *att, *y, *mb, *hb, *x1, *x2;
    cudaGetSymbolAddress((void**)&qkv, g_qkv);
    cudaGetSymbolAddress((void**)&z,   g_z);
    cudaGetSymbolAddress((void**)&s,   g_s);
    cudaGetSymbolAddress((void**)&bm,  g_bm);
    cudaGetSymbolAddress((void**)&att, g_att);
    cudaGetSymbolAddress((void**)&y,   g_y);
    cudaGetSymbolAddress((void**)&mb,  g_m);
    cudaGetSymbolAddress((void**)&hb,  g_h);
    cudaGetSymbolAddress((void**)&x1,  g_x1);
    cudaGetSymbolAddress((void**)&x2,  g_x2);

    cudaFuncSetAttribute(gemm_tc<0,1,false,false,false>, cudaFuncAttributeMaxDynamicSharedMemorySize, SMEM_DYN);
    cudaFuncSetAttribute(gemm_tc<0,0,true, false,false>, cudaFuncAttributeMaxDynamicSharedMemorySize, SMEM_DYN);
    cudaFuncSetAttribute(gemm_tc<1,1,false,false,false>, cudaFuncAttributeMaxDynamicSharedMemorySize, SMEM_DYN);
    cudaFuncSetAttribute(gemm_tc<1,0,true, false,false>, cudaFuncAttributeMaxDynamicSharedMemorySize, SMEM_DYN);
    cudaFuncSetAttribute(gemm_tc<0,0,false,true, false>, cudaFuncAttributeMaxDynamicSharedMemorySize, SMEM_DYN);
    cudaFuncSetAttribute(gemm_tc<0,0,true, false,true >, cudaFuncAttributeMaxDynamicSharedMemorySize, SMEM_DYN);

    const ll DS = (ll)DD * SS;

    auto run_block = [&](const float* qp0, const float* qp1, const float* qp2,
                         const float* W1, const float* W2,
                         const float* cw1, const float* cw2) {
        const float* qp[3] = {qp0, qp1, qp2};
        for (int q = 0; q < 3; q++) {
            // z[h] = relu(qkv[q]) @ W1[h,q]^T
            gemm_tc<0,0,true,false,false>
                <<<dim3(MIDD / 128, DD / 128, HH), 256, SMEM_DYN>>>(
                    qp[q], W1 + (ll)q * MIDD * SS, z,
                    DD, MIDD, SS, 0, 3ll * MIDD * SS, (ll)DD * MIDD);
            // s[h,q] = relu(z[h]) @ W2[h,q]^T
            gemm_tc<0,0,true,false,false>
                <<<dim3(SS / 128, DD / 128, HH), 256, SMEM_DYN>>>(
                    z, W2 + (ll)q * SS * MIDD, s + (ll)q * DS,
                    DD, SS, MIDD, (ll)DD * MIDD, 3ll * SS * MIDD, 3ll * DS);
        }
        // b[h][i][j] = sum_d k[d][i] q[d][j]     A=k (K,M), B=q (K,N)
        gemm_tc<1,1,false,false,false>
            <<<dim3(SS / 128, SS / 128, HH), 256, SMEM_DYN>>>(
                s + DS, s, bm, SS, SS, DD, 3ll * DS, 3ll * DS, (ll)SS * SS);
        // att[h][d][t] = sum_s v[d][s] b[s][t]   A=v (M,K), B=b (K,N)
        gemm_tc<0,1,false,false,false>
            <<<dim3(SS / 128, DD / 128, HH), 256, SMEM_DYN>>>(
                s + 2ll * DS, bm, att, DD, SS, SS, 3ll * DS, (ll)SS * SS, DS);
        // y[s][m] = sum_c relu(att[c][s]) cw1[m][c]   A=att (K,M), B=cw1 (N,K)
        gemm_tc<1,0,true,false,false>
            <<<dim3(MIDD / 128, SS / 128, 1), 256, SMEM_DYN>>>(
                att, cw1, y, SS, MIDD, HH * DD, 0, 0, 0);
        // m[d][s] = sum_m cw2[d][m] relu(y[s][m])     A=cw2 (M,K), B=y (N,K)
        gemm_tc<0,0,false,true,false>
            <<<dim3(SS / 128, DD / 128, 1), 256, SMEM_DYN>>>(
                cw2, y, mb, DD, SS, MIDD, 0, 0, 0);
    };

    // qkv1[q] = w_qkv1[q] @ inp    A=W (M,K), B=inp (K,N)
    gemm_tc<0,1,false,false,false>
        <<<dim3(SS / 128, DD / 128, 3), 256, SMEM_DYN>>>(
            w_qkv1, inp, qkv, DD, SS, DD, (ll)DD * DD, 0, DS);

    run_block(qkv, qkv + DS, qkv + 2ll * DS, mh1_W1, mh1_W2, c1_w1, c1_w2);
    add_ln_k<<<DD, 256>>>(inp, mb, gamma, beta, hb);

    // q2 = w_qkv2[0] @ h1
    gemm_tc<0,1,false,false,false>
        <<<dim3(SS / 128, DD / 128, 1), 256, SMEM_DYN>>>(
            w_qkv2, hb, qkv, DD, SS, DD, 0, 0, 0);

    run_block(qkv, enc_k, enc_v, mh2_W1, mh2_W2, c2_w1, c2_w2);
    add_ln_k<<<DD, 256>>>(inp, mb, gamma, beta, hb);

    // x1 = relu(h2) @ l1_w1^T
    gemm_tc<0,0,true,false,false>
        <<<dim3(MIDD / 128, DD / 128, 1), 256, SMEM_DYN>>>(
            hb, l1_w1, x1, DD, MIDD, SS, 0, 0, 0);
    // x2 = relu(x1) @ l1_w2^T
    gemm_tc<0,0,true,false,false>
        <<<dim3(SOUT / 128, DD / 128, 1), 256, SMEM_DYN>>>(
            x1, l1_w2, x2, DD, SOUT, MIDD, 0, 0, 0);
    // y1 = relu(x2) @ l2_w1^T
    gemm_tc<0,0,true,false,false>
        <<<dim3(MIDD / 128, DD / 128, 1), 256, SMEM_DYN>>>(
            x2, l2_w1, x1, DD, MIDD, SOUT, 0, 0, 0);
    // out = tanh(relu(y1) @ l2_w2^T)
    gemm_tc<0,0,true,false,true>
        <<<dim3(SOUT / 128, DD / 128, 1), 256, SMEM_DYN>>>(
            x1, l2_w2, out, DD, SOUT, MIDD, 0, 0, 0);
}

// round 11
// speedup vs baseline: 2.7750x; 1.0919x over previous
#include <cuda_runtime.h>
#include <cstdint>

#define HH 8
#define DD 1024
#define SS 1024
#define MIDD 2048
#define SOUT 512

typedef long long ll;

// ---------------- scratch (device globals; no allocation allowed) ----------
// packed (lo_bf16<<16 | hi_bf16) intermediates
__device__ uint32_t p_qkv[3ll * DD * SS];
__device__ uint32_t p_z[(ll)HH * DD * MIDD];
__device__ uint32_t p_s[(ll)HH * 3 * DD * SS];
__device__ uint32_t p_bm[(ll)HH * SS * SS];
__device__ uint32_t p_att[(ll)HH * DD * SS];
__device__ uint32_t p_y[(ll)SS * MIDD];
__device__ uint32_t p_h[(ll)DD * SS];
__device__ uint32_t p_x1[(ll)DD * MIDD];
__device__ uint32_t p_x2[(ll)DD * SOUT];
__device__ float    g_m[(ll)DD * SS];
// packed inputs / weights
__device__ uint32_t p_inp [(ll)DD * SS];
__device__ uint32_t p_enck[(ll)DD * SS];
__device__ uint32_t p_encv[(ll)DD * SS];
__device__ uint32_t p_wqkv1[3ll * DD * DD];
__device__ uint32_t p_wqkv2[(ll)DD * DD];
__device__ uint32_t p_W1a[(ll)HH * 3 * MIDD * SS];
__device__ uint32_t p_W2a[(ll)HH * 3 * SS * MIDD];
__device__ uint32_t p_W1b[(ll)HH * 3 * MIDD * SS];
__device__ uint32_t p_W2b[(ll)HH * 3 * SS * MIDD];
__device__ uint32_t p_c1w1[(ll)MIDD * HH * DD];
__device__ uint32_t p_c2w1[(ll)MIDD * HH * DD];
__device__ uint32_t p_c1w2[(ll)DD * MIDD];
__device__ uint32_t p_c2w2[(ll)DD * MIDD];
__device__ uint32_t p_l1w1[(ll)MIDD * SS];
__device__ uint32_t p_l1w2[(ll)SOUT * MIDD];
__device__ uint32_t p_l2w1[(ll)MIDD * SOUT];
__device__ uint32_t p_l2w2[(ll)SOUT * MIDD];

// ---------------- PTX helpers (base sm_103 features only) -------------------
__device__ __forceinline__ uint32_t smem_u32(const void* p) {
    uint32_t a;
    asm("{ .reg .u64 t; cvta.to.shared.u64 t, %1; cvt.u32.u64 %0, t; }"
        : "=r"(a) : "l"(p));
    return a;
}
__device__ __forceinline__ void cpa16(uint32_t dst, const void* src) {
    asm volatile("cp.async.cg.shared.global [%0], [%1], 16;"
                 :: "r"(dst), "l"(src) : "memory");
}
__device__ __forceinline__ void cpa4(uint32_t dst, const void* src) {
    asm volatile("cp.async.ca.shared.global [%0], [%1], 4;"
                 :: "r"(dst), "l"(src) : "memory");
}
__device__ __forceinline__ void cp_commit() {
    asm volatile("cp.async.commit_group;" ::: "memory");
}
template<int NG>
__device__ __forceinline__ void cp_wait() {
    asm volatile("cp.async.wait_group %0;" :: "n"(NG) : "memory");
}
__device__ __forceinline__ uint32_t prmtb(uint32_t a, uint32_t b, uint32_t s) {
    uint32_t r;
    asm("prmt.b32 %0, %1, %2, %3;" : "=r"(r) : "r"(a), "r"(b), "r"(s));
    return r;
}

// pack two floats -> two packed words (lo<<16|hi each)
template<bool RELU>
__device__ __forceinline__ void pack2(float2 v, uint32_t& w0, uint32_t& w1) {
    if (RELU) { v.x = fmaxf(v.x, 0.f); v.y = fmaxf(v.y, 0.f); }
    uint32_t hp, lp;
    asm("cvt.rn.bf16x2.f32 %0, %1, %2;" : "=r"(hp) : "f"(v.y), "f"(v.x));
    const float hx = __uint_as_float(hp << 16);
    const float hy = __uint_as_float(hp & 0xffff0000u);
    asm("cvt.rn.bf16x2.f32 %0, %1, %2;" : "=r"(lp) : "f"(v.y - hy), "f"(v.x - hx));
    w0 = prmtb(hp, lp, 0x5410);
    w1 = prmtb(hp, lp, 0x7632);
}

// unpack two consecutive packed elems -> bf16x2 hi-pair + lo-pair (2 PRMT)
__device__ __forceinline__ void fragp(const uint32_t* p, uint32_t& hi, uint32_t& lo) {
    const uint2 e = *(const uint2*)p;
    hi = prmtb(e.x, e.y, 0x5410);
    lo = prmtb(e.x, e.y, 0x7632);
}

__device__ __forceinline__ void mma16(float* d, const uint32_t* a, const uint32_t* b) {
    asm volatile(
        "mma.sync.aligned.m16n8k16.row.col.f32.bf16.bf16.f32 "
        "{%0,%1,%2,%3}, {%4,%5,%6,%7}, {%8,%9}, {%0,%1,%2,%3};"
        : "+f"(d[0]), "+f"(d[1]), "+f"(d[2]), "+f"(d[3])
        : "r"(a[0]), "r"(a[1]), "r"(a[2]), "r"(a[3]), "r"(b[0]), "r"(b[1]));
}

// ---------------- elementwise pack kernel -----------------------------------
template<bool RELU>
__global__ __launch_bounds__(256) void pack_k(
    const float4* __restrict__ src, uint4* __restrict__ dst, int n4)
{
    const int i = blockIdx.x * 256 + threadIdx.x;
    if (i >= n4) return;
    const float4 v = src[i];
    uint4 o;
    pack2<RELU>(make_float2(v.x, v.y), o.x, o.y);
    pack2<RELU>(make_float2(v.z, v.w), o.z, o.w);
    dst[i] = o;
}

// ---------------- packed bf16x3 mma.sync GEMM -------------------------------
// D[m][n] = sum_k a[m][k] * b[n][k], operands pre-split packed bf16 hi/lo.
//   LA/LB: 0 = row-major (M,K)/(N,K); 1 = transposed (K,M)/(K,N).
//   EP: 0 = fp32 out, 1 = fp32 tanh out, 2 = packed out, 3 = packed+relu out.
// M,N mult of 128; K mult of 32. 256 threads (8 warps, 2x4 warp grid).

#define STR     40
#define TILE_W  (128 * STR)         // uint32 per operand stage
#define STAGE_B (TILE_W * 4)        // 20480 bytes
#define SMEM_DYN (4 * STAGE_B)      // 81920 bytes

template<int LA, int LB, int EP>
__global__ __launch_bounds__(256, 2) void gemm_p(
    const uint32_t* __restrict__ Ag, const uint32_t* __restrict__ Bg, void* Cg,
    int M, int N, int K, ll sA, ll sB, ll sC)
{
    extern __shared__ __align__(16) uint32_t smem[];
    const uint32_t sb = smem_u32(smem);

    const uint32_t* A = Ag + (ll)blockIdx.z * sA;
    const uint32_t* B = Bg + (ll)blockIdx.z * sB;
    const int m0 = blockIdx.y * 128;
    const int n0 = blockIdx.x * 128;

    const int tid = threadIdx.x;
    const int wid = tid >> 5, lid = tid & 31;
    const int wm = wid >> 2, wn = wid & 3;
    const int g = lid >> 2, tg = lid & 3;

    float acc[4][4][4];
    #pragma unroll
    for (int mi = 0; mi < 4; mi++)
        #pragma unroll
        for (int ni = 0; ni < 4; ni++)
            #pragma unroll
            for (int r = 0; r < 4; r++) acc[mi][ni][r] = 0.f;

    auto issue = [&](int t) {
        const int st = t & 1;
        const uint32_t abase = sb + (uint32_t)(st * 2) * STAGE_B;
        const uint32_t bbase = abase + STAGE_B;
        const int k0 = t << 5;
        if (LA == 0) {
            #pragma unroll
            for (int i = 0; i < 4; i++) {
                int idx = tid + i * 256;
                int r = idx >> 3, kq = (idx & 7) << 2;
                cpa16(abase + (uint32_t)(r * STR + kq) * 4,
                      A + (ll)(m0 + r) * K + k0 + kq);
            }
        } else {
            #pragma unroll
            for (int i = 0; i < 16; i++) {
                int idx = tid + i * 256;
                int m = idx & 127, k = idx >> 7;
                cpa4(abase + (uint32_t)(m * STR + k) * 4,
                     A + (ll)(k0 + k) * M + m0 + m);
            }
        }
        if (LB == 0) {
            #pragma unroll
            for (int i = 0; i < 4; i++) {
                int idx = tid + i * 256;
                int r = idx >> 3, kq = (idx & 7) << 2;
                cpa16(bbase + (uint32_t)(r * STR + kq) * 4,
                      B + (ll)(n0 + r) * K + k0 + kq);
            }
        } else {
            #pragma unroll
            for (int i = 0; i < 16; i++) {
                int idx = tid + i * 256;
                int n = idx & 127, k = idx >> 7;
                cpa4(bbase + (uint32_t)(n * STR + k) * 4,
                     B + (ll)(k0 + k) * N + n0 + n);
            }
        }
    };

    const int T = K >> 5;
    issue(0);
    cp_commit();

    for (int t = 0; t < T; t++) {
        if (t + 1 < T) { issue(t + 1); cp_commit(); cp_wait<1>(); }
        else           { cp_wait<0>(); }
        __syncthreads();

        const uint32_t* As = smem + (t & 1) * 2 * TILE_W;
        const uint32_t* Bs = As + TILE_W;

        #pragma unroll
        for (int ks = 0; ks < 2; ks++) {
            const int kb = ks * 16;
            uint32_t bh[4][2], bl[4][2];
            #pragma unroll
            for (int ni = 0; ni < 4; ni++) {
                const uint32_t* p = Bs + (wn * 32 + ni * 8 + g) * STR + kb + 2 * tg;
                fragp(p,     bh[ni][0], bl[ni][0]);
                fragp(p + 8, bh[ni][1], bl[ni][1]);
            }
            #pragma unroll
            for (int mi = 0; mi < 4; mi++) {
                uint32_t ah[4], al[4];
                const uint32_t* p = As + (wm * 64 + mi * 16 + g) * STR + kb + 2 * tg;
                fragp(p,               ah[0], al[0]);
                fragp(p + 8 * STR,     ah[1], al[1]);
                fragp(p + 8,           ah[2], al[2]);
                fragp(p + 8 * STR + 8, ah[3], al[3]);
                #pragma unroll
                for (int ni = 0; ni < 4; ni++) {
                    mma16(acc[mi][ni], ah, bh[ni]);
                    mma16(acc[mi][ni], ah, bl[ni]);
                    mma16(acc[mi][ni], al, bh[ni]);
                }
            }
        }
        __syncthreads();
    }

    // ---- epilogue ----
    #pragma unroll
    for (int mi = 0; mi < 4; mi++) {
        #pragma unroll
        for (int ni = 0; ni < 4; ni++) {
            const int r0 = m0 + wm * 64 + mi * 16 + g;
            const int c  = n0 + wn * 32 + ni * 8 + 2 * tg;
            float2 v0 = make_float2(acc[mi][ni][0], acc[mi][ni][1]);
            float2 v1 = make_float2(acc[mi][ni][2], acc[mi][ni][3]);
            if (EP <= 1) {
                float* C = (float*)Cg + (ll)blockIdx.z * sC;
                if (EP == 1) {
                    v0.x = tanhf(v0.x); v0.y = tanhf(v0.y);
                    v1.x = tanhf(v1.x); v1.y = tanhf(v1.y);
                }
                *(float2*)(C + (ll)r0 * N + c)       = v0;
                *(float2*)(C + (ll)(r0 + 8) * N + c) = v1;
            } else {
                uint32_t* C = (uint32_t*)Cg + (ll)blockIdx.z * sC;
                uint2 w0, w1;
                pack2<EP == 3>(v0, w0.x, w0.y);
                pack2<EP == 3>(v1, w1.x, w1.y);
                *(uint2*)(C + (ll)r0 * N + c)       = w0;
                *(uint2*)(C + (ll)(r0 + 8) * N + c) = w1;
            }
        }
    }
}

// ---------------- fused residual-add + LayerNorm -> packed output -----------
template<bool RELU>
__global__ __launch_bounds__(256) void add_ln_k(
    const float* __restrict__ x, const float* __restrict__ m,
    const float* __restrict__ g, const float* __restrict__ b,
    uint32_t* __restrict__ o)
{
    const int row = blockIdx.x;
    const ll off = (ll)row * SS;
    float2 v[2];
    float sum = 0.f, sq = 0.f;
    #pragma unroll
    for (int j = 0; j < 2; j++) {
        int i2 = threadIdx.x * 2 + j * 512;
        float2 xv = *(const float2*)(x + off + i2);
        float2 mv = *(const float2*)(m + off + i2);
        v[j] = make_float2(xv.x + mv.x, xv.y + mv.y);
        sum += v[j].x + v[j].y;
        sq  += v[j].x * v[j].x + v[j].y * v[j].y;
    }
    #pragma unroll
    for (int o2 = 16; o2; o2 >>= 1) {
        sum += __shfl_xor_sync(0xffffffffu, sum, o2);
        sq  += __shfl_xor_sync(0xffffffffu, sq,  o2);
    }
    __shared__ float rs[8], rq[8];
    const int w = threadIdx.x >> 5, l = threadIdx.x & 31;
    if (l == 0) { rs[w] = sum; rq[w] = sq; }
    __syncthreads();
    if (w == 0) {
        float s2 = (l < 8) ? rs[l] : 0.f;
        float q2 = (l < 8) ? rq[l] : 0.f;
        #pragma unroll
        for (int o2 = 4; o2; o2 >>= 1) {
            s2 += __shfl_xor_sync(0xffffffffu, s2, o2);
            q2 += __shfl_xor_sync(0xffffffffu, q2, o2);
        }
        if (l == 0) { rs[0] = s2; rq[0] = q2; }
    }
    __syncthreads();
    const float mu  = rs[0] * (1.f / SS);
    const float var = rq[0] * (1.f / SS) - mu * mu;
    const float inv = rsqrtf(var + 1e-6f);
    #pragma unroll
    for (int j = 0; j < 2; j++) {
        int i2 = threadIdx.x * 2 + j * 512;
        float2 gv = *(const float2*)(g + i2);
        float2 bv = *(const float2*)(b + i2);
        float2 t = make_float2((v[j].x - mu) * inv * gv.x + bv.x,
                               (v[j].y - mu) * inv * gv.y + bv.y);
        uint2 wo;
        pack2<RELU>(t, wo.x, wo.y);
        *(uint2*)(o + off + i2) = wo;
    }
}

// ---------------- host orchestration ----------------------------------------
extern "C" void kernel_launch(void* const* d_in, const int* in_sizes, int n_in,
                              void* d_out, int out_size)
{
    const float* inp    = (const float*)d_in[0];
    const float* enc_k  = (const float*)d_in[1];
    const float* enc_v  = (const float*)d_in[2];
    const float* w_qkv1 = (const float*)d_in[3];
    const float* w_qkv2 = (const float*)d_in[4];
    const float* mh1_W1 = (const float*)d_in[5];
    const float* mh1_W2 = (const float*)d_in[6];
    const float* mh2_W1 = (const float*)d_in[7];
    const float* mh2_W2 = (const float*)d_in[8];
    const float* c1_w1  = (const float*)d_in[9];
    const float* c1_w2  = (const float*)d_in[10];
    const float* c2_w1  = (const float*)d_in[11];
    const float* c2_w2  = (const float*)d_in[12];
    const float* l1_w1  = (const float*)d_in[13];
    const float* l1_w2  = (const float*)d_in[14];
    const float* l2_w1  = (const float*)d_in[15];
    const float* l2_w2  = (const float*)d_in[16];
    const float* gamma  = (const float*)d_in[17];
    const float* beta   = (const float*)d_in[18];
    float* out = (float*)d_out;

    uint32_t *qkv, *z, *s, *bm, *att, *y, *hb, *x1, *x2;
    uint32_t *pinp, *penck, *pencv, *pw1, *pw2;
    uint32_t *W1a, *W2a, *W1b, *W2b, *c1a, *c2a, *c1b, *c2b;
    uint32_t *lw11, *lw12, *lw21, *lw22;
    float* mb;
    cudaGetSymbolAddress((void**)&qkv,  p_qkv);
    cudaGetSymbolAddress((void**)&z,    p_z);
    cudaGetSymbolAddress((void**)&s,    p_s);
    cudaGetSymbolAddress((void**)&bm,   p_bm);
    cudaGetSymbolAddress((void**)&att,  p_att);
    cudaGetSymbolAddress((void**)&y,    p_y);
    cudaGetSymbolAddress((void**)&hb,   p_h);
    cudaGetSymbolAddress((void**)&x1,   p_x1);
    cudaGetSymbolAddress((void**)&x2,   p_x2);
    cudaGetSymbolAddress((void**)&mb,   g_m);
    cudaGetSymbolAddress((void**)&pinp,  p_inp);
    cudaGetSymbolAddress((void**)&penck, p_enck);
    cudaGetSymbolAddress((void**)&pencv, p_encv);
    cudaGetSymbolAddress((void**)&pw1,   p_wqkv1);
    cudaGetSymbolAddress((void**)&pw2,   p_wqkv2);
    cudaGetSymbolAddress((void**)&W1a,   p_W1a);
    cudaGetSymbolAddress((void**)&W2a,   p_W2a);
    cudaGetSymbolAddress((void**)&W1b,   p_W1b);
    cudaGetSymbolAddress((void**)&W2b,   p_W2b);
    cudaGetSymbolAddress((void**)&c1a,   p_c1w1);
    cudaGetSymbolAddress((void**)&c2a,   p_c2w1);
    cudaGetSymbolAddress((void**)&c1b,   p_c1w2);
    cudaGetSymbolAddress((void**)&c2b,   p_c2w2);
    cudaGetSymbolAddress((void**)&lw11,  p_l1w1);
    cudaGetSymbolAddress((void**)&lw12,  p_l1w2);
    cudaGetSymbolAddress((void**)&lw21,  p_l2w1);
    cudaGetSymbolAddress((void**)&lw22,  p_l2w2);

    cudaFuncSetAttribute(gemm_p<0,0,0>, cudaFuncAttributeMaxDynamicSharedMemorySize, SMEM_DYN);
    cudaFuncSetAttribute(gemm_p<0,0,1>, cudaFuncAttributeMaxDynamicSharedMemorySize, SMEM_DYN);
    cudaFuncSetAttribute(gemm_p<0,0,2>, cudaFuncAttributeMaxDynamicSharedMemorySize, SMEM_DYN);
    cudaFuncSetAttribute(gemm_p<0,0,3>, cudaFuncAttributeMaxDynamicSharedMemorySize, SMEM_DYN);
    cudaFuncSetAttribute(gemm_p<0,1,3>, cudaFuncAttributeMaxDynamicSharedMemorySize, SMEM_DYN);
    cudaFuncSetAttribute(gemm_p<1,1,2>, cudaFuncAttributeMaxDynamicSharedMemorySize, SMEM_DYN);
    cudaFuncSetAttribute(gemm_p<1,0,3>, cudaFuncAttributeMaxDynamicSharedMemorySize, SMEM_DYN);

    auto pk = [&](const float* src, uint32_t* dst, ll n, bool relu) {
        const int n4 = (int)(n >> 2);
        const int gr = (n4 + 255) / 256;
        if (relu) pack_k<true ><<<gr, 256>>>((const float4*)src, (uint4*)dst, n4);
        else      pack_k<false><<<gr, 256>>>((const float4*)src, (uint4*)dst, n4);
    };

    const ll DS = (ll)DD * SS;
    const ll WSZ = (ll)HH * 3 * MIDD * SS;

    // ---- one-time packing of inputs & weights ----
    pk(inp,    pinp,  DS, false);
    pk(enc_k,  penck, DS, true);        // consumed only via relu
    pk(enc_v,  pencv, DS, true);
    pk(w_qkv1, pw1,   3ll * DD * DD, false);
    pk(w_qkv2, pw2,   (ll)DD * DD,   false);   // only slot 0 needed
    pk(mh1_W1, W1a,   WSZ, false);
    pk(mh1_W2, W2a,   WSZ, false);
    pk(mh2_W1, W1b,   WSZ, false);
    pk(mh2_W2, W2b,   WSZ, false);
    pk(c1_w1,  c1a,   (ll)MIDD * HH * DD, false);
    pk(c2_w1,  c2a,   (ll)MIDD * HH * DD, false);
    pk(c1_w2,  c1b,   (ll)DD * MIDD, false);
    pk(c2_w2,  c2b,   (ll)DD * MIDD, false);
    pk(l1_w1,  lw11,  (ll)MIDD * SS,   false);
    pk(l1_w2,  lw12,  (ll)SOUT * MIDD, false);
    pk(l2_w1,  lw21,  (ll)MIDD * SOUT, false);
    pk(l2_w2,  lw22,  (ll)SOUT * MIDD, false);

    auto run_block = [&](const uint32_t* qp0, const uint32_t* qp1, const uint32_t* qp2,
                         const uint32_t* W1, const uint32_t* W2,
                         const uint32_t* cw1, const uint32_t* cw2) {
        const uint32_t* qp[3] = {qp0, qp1, qp2};
        for (int q = 0; q < 3; q++) {
            // z[h] = relu(qkv[q]) @ W1[h,q]^T  -> packed+relu
            gemm_p<0,0,3><<<dim3(MIDD / 128, DD / 128, HH), 256, SMEM_DYN>>>(
                qp[q], W1 + (ll)q * MIDD * SS, z,
                DD, MIDD, SS, 0, 3ll * MIDD * SS, (ll)DD * MIDD);
            // s[h,q] = relu(z[h]) @ W2[h,q]^T  -> packed plain
            gemm_p<0,0,2><<<dim3(SS / 128, DD / 128, HH), 256, SMEM_DYN>>>(
                z, W2 + (ll)q * SS * MIDD, s + (ll)q * DS,
                DD, SS, MIDD, (ll)DD * MIDD, 3ll * SS * MIDD, 3ll * DS);
        }
        // b[h] = k^T q  -> packed plain
        gemm_p<1,1,2><<<dim3(SS / 128, SS / 128, HH), 256, SMEM_DYN>>>(
            s + DS, s, bm, SS, SS, DD, 3ll * DS, 3ll * DS, (ll)SS * SS);
        // att[h] = v @ b  -> packed+relu (consumer applies relu)
        gemm_p<0,1,3><<<dim3(SS / 128, DD / 128, HH), 256, SMEM_DYN>>>(
            s + 2ll * DS, bm, att, DD, SS, SS, 3ll * DS, (ll)SS * SS, DS);
        // y = relu(cat)^T @ cw1^T  -> packed+relu
        gemm_p<1,0,3><<<dim3(MIDD / 128, SS / 128, 1), 256, SMEM_DYN>>>(
            att, cw1, y, SS, MIDD, HH * DD, 0, 0, 0);
        // m = cw2 @ relu(y)^T  -> fp32 (feeds layernorm)
        gemm_p<0,0,0><<<dim3(SS / 128, DD / 128, 1), 256, SMEM_DYN>>>(
            cw2, y, mb, DD, SS, MIDD, 0, 0, 0);
    };

    // qkv1[q] = w_qkv1[q] @ inp  -> packed+relu
    gemm_p<0,1,3><<<dim3(SS / 128, DD / 128, 3), 256, SMEM_DYN>>>(
        pw1, pinp, qkv, DD, SS, DD, (ll)DD * DD, 0, DS);

    run_block(qkv, qkv + DS, qkv + 2ll * DS, W1a, W2a, c1a, c1b);
    add_ln_k<false><<<DD, 256>>>(inp, mb, gamma, beta, hb);   // h1 packed plain

    // q2 = w_qkv2[0] @ h1  -> packed+relu
    gemm_p<0,1,3><<<dim3(SS / 128, DD / 128, 1), 256, SMEM_DYN>>>(
        pw2, hb, qkv, DD, SS, DD, 0, 0, 0);

    run_block(qkv, penck, pencv, W1b, W2b, c2a, c2b);
    add_ln_k<true><<<DD, 256>>>(inp, mb, gamma, beta, hb);    // h2 packed+relu

    // x1 = relu(h2) @ l1_w1^T  -> packed+relu
    gemm_p<0,0,3><<<dim3(MIDD / 128, DD / 128, 1), 256, SMEM_DYN>>>(
        hb, lw11, x1, DD, MIDD, SS, 0, 0, 0);
    // x2 = relu(x1) @ l1_w2^T  -> packed+relu
    gemm_p<0,0,3><<<dim3(SOUT / 128, DD / 128, 1), 256, SMEM_DYN>>>(
        x1, lw12, x2, DD, SOUT, MIDD, 0, 0, 0);
    // y1 = relu(x2) @ l2_w1^T  -> packed+relu (reuse x1)
    gemm_p<0,0,3><<<dim3(MIDD / 128, DD / 128, 1), 256, SMEM_DYN>>>(
        x2, lw21, x1, DD, MIDD, SOUT, 0, 0, 0);
    // out = tanh(relu(y1) @ l2_w2^T)  -> fp32 + tanh
    gemm_p<0,0,1><<<dim3(SOUT / 128, DD / 128, 1), 256, SMEM_DYN>>>(
        x1, lw22, out, DD, SOUT, MIDD, 0, 0, 0);
}